// round 15
// baseline (speedup 1.0000x reference)
#include <cuda_runtime.h>
#include <cuda_fp16.h>

// CRF NLL mean — B=256, S=512, T=64.
// Bidirectional split (fwd: transitions 1..255, bwd: 511..256) combined at the
// midpoint. One self-contained warp per chain. R15: block = 8 warps =
// 4 batches x {fwd,bwd}, grid = 64 -> 1 block/SM, TWO independent chains per
// SMSP (latency hiding). Parity-split fp16 dot: publish natural pair
// (u_2t,u_2t+1) as one half2 (STS.32), 8 LDS.128 + 64 HFMA2 per step.

constexpr int NT  = 64;
constexpr int NB  = 256;
constexpr int NS  = 512;

__device__ float g_llh[NB];
__device__ int   g_cnt = 0;

__device__ __forceinline__ float warp_sum_f(float v) {
#pragma unroll
    for (int o = 16; o > 0; o >>= 1) v += __shfl_down_sync(0xffffffffu, v, o);
    return v;
}
__device__ __forceinline__ int warp_sum_i(int v) {
#pragma unroll
    for (int o = 16; o > 0; o >>= 1) v += __shfl_down_sync(0xffffffffu, v, o);
    return v;
}

// Parity-split 64-contraction in fp16. pb: 32 half2 words, word k = (u_2k,u_2k+1).
// EA[k] = (E_{2k}->j0, E_{2k+1}->j0), EB likewise for j1. Outputs = lo+hi.
__device__ __forceinline__ float2 dot_fp16(
    const unsigned int* __restrict__ pb,
    const __half2* __restrict__ EA, const __half2* __restrict__ EB)
{
    __half2 z = __float2half2_rn(0.0f);
    __half2 a0=z,a1=z,a2=z,a3=z,b0=z,b1=z,b2=z,b3=z;
    const uint4* p4 = (const uint4*)pb;   // 8 x 16B broadcast reads
#pragma unroll
    for (int g = 0; g < 8; g += 2) {
        uint4 q0 = p4[g];
        uint4 q1 = p4[g + 1];
        a0 = __hfma2(*(const __half2*)&q0.x, EA[4*g + 0], a0);
        b0 = __hfma2(*(const __half2*)&q0.x, EB[4*g + 0], b0);
        a1 = __hfma2(*(const __half2*)&q0.y, EA[4*g + 1], a1);
        b1 = __hfma2(*(const __half2*)&q0.y, EB[4*g + 1], b1);
        a2 = __hfma2(*(const __half2*)&q0.z, EA[4*g + 2], a2);
        b2 = __hfma2(*(const __half2*)&q0.z, EB[4*g + 2], b2);
        a3 = __hfma2(*(const __half2*)&q0.w, EA[4*g + 3], a3);
        b3 = __hfma2(*(const __half2*)&q0.w, EB[4*g + 3], b3);
        a0 = __hfma2(*(const __half2*)&q1.x, EA[4*g + 4], a0);
        b0 = __hfma2(*(const __half2*)&q1.x, EB[4*g + 4], b0);
        a1 = __hfma2(*(const __half2*)&q1.y, EA[4*g + 5], a1);
        b1 = __hfma2(*(const __half2*)&q1.y, EB[4*g + 5], b1);
        a2 = __hfma2(*(const __half2*)&q1.z, EA[4*g + 6], a2);
        b2 = __hfma2(*(const __half2*)&q1.z, EB[4*g + 6], b2);
        a3 = __hfma2(*(const __half2*)&q1.w, EA[4*g + 7], a3);
        b3 = __hfma2(*(const __half2*)&q1.w, EB[4*g + 7], b3);
    }
    a0 = __hadd2(a0, a1); a2 = __hadd2(a2, a3); a0 = __hadd2(a0, a2);
    b0 = __hadd2(b0, b1); b2 = __hadd2(b2, b3); b0 = __hadd2(b0, b2);
    float2 fa = __half22float2(a0);
    float2 fb = __half22float2(b0);
    return make_float2(fa.x + fa.y, fb.x + fb.y);
}

__global__ __launch_bounds__(256, 1) void crf_forward_kernel(
    const float* __restrict__ em,        // (B,S,T)
    const int*   __restrict__ tags32,    // (B,S) int32 (or int64 viewed as pairs)
    const int*   __restrict__ mask,      // (B,S)
    const float* __restrict__ startT,
    const float* __restrict__ endT,
    const float* __restrict__ trans,
    float*       __restrict__ out)
{
    const int tid = threadIdx.x;
    const int w   = tid >> 5;            // warp 0..7; SMSP = w & 3
    const int t   = tid & 31;            // lane; owns outputs j0=2t, j1=2t+1
    const int bs  = w >> 1;              // batch slot 0..3
    const int dir = w & 1;               // 0 = forward, 1 = backward
    const int b   = blockIdx.x * 4 + bs;

    // per-warp double-buffered published vector: 32 half2 words = 128B
    __shared__ __align__(16) unsigned int ubuf[8][2][32];
    __shared__ float fv[4][2][NT];
    __shared__ float nsh[8];
    __shared__ int   msh[8], eosh[8];

    bool is64 = true;
#pragma unroll
    for (int k = 0; k < 16; k++) is64 &= (tags32[2 * k + 1] == 0);

    const int j0 = 2 * t, j1 = 2 * t + 1;

    // E in fp16, parity-packed over contraction dim (64 half2 = 64 regs)
    __half2 EA[32], EB[32];
    if (dir == 0) {
        // fwd: contraction over rows i; outputs = columns j0/j1
#pragma unroll
        for (int k = 0; k < 32; k++) {
            float a0 = __expf(trans[(2 * k)     * NT + j0]);
            float a1 = __expf(trans[(2 * k + 1) * NT + j0]);
            float b0 = __expf(trans[(2 * k)     * NT + j1]);
            float b1 = __expf(trans[(2 * k + 1) * NT + j1]);
            EA[k] = __floats2half2_rn(a0, a1);
            EB[k] = __floats2half2_rn(b0, b1);
        }
    } else {
        // bwd: contraction over columns; outputs = rows j0/j1
#pragma unroll
        for (int k = 0; k < 32; k++) {
            float2 rA = *(const float2*)(trans + j0 * NT + 2 * k);
            float2 rB = *(const float2*)(trans + j1 * NT + 2 * k);
            EA[k] = __floats2half2_rn(__expf(rA.x), __expf(rA.y));
            EB[k] = __floats2half2_rn(__expf(rB.x), __expf(rB.y));
        }
    }

    const float* emb  = em + (size_t)b * NS * NT;
    const int*   mrow = mask + b * NS;
    unsigned int* myb0 = ubuf[w][0];
    unsigned int* myb1 = ubuf[w][1];

    const int  srow0 = dir ? (NS - 1) : 0;
    const int  sstep = dir ? -1 : 1;
    const float* ep0 = emb + srow0 * NT + j0;
    const long rstride = (long)sstep * NT;

    float ua, ub;                         // fp32 chain state
    int eoff = 0;
    if (dir == 0) {
        float2 st2 = *(const float2*)(startT + j0);
        float2 e0v = *(const float2*)(emb + j0);
        ua = __expf(st2.x + e0v.x);
        ub = __expf(st2.y + e0v.y);
    } else {
        float2 en2 = *(const float2*)(endT + j0);
        ua = __expf(en2.x);
        ub = __expf(en2.y);
    }
    const int isBwd = dir;

    // depth-4 rotating prefetch (always in-bounds)
    float2 ev[4]; int mv[4];
#pragma unroll
    for (int k = 0; k < 4; k++) {
        ev[k] = *(const float2*)(ep0 + (long)k * rstride);
        mv[k] = mrow[srow0 + k * sstep];
    }
    if (dir == 0) mv[0] = 0;              // fwd dummy step

    for (int ko = 0; ko < 64; ko++) {
#pragma unroll
        for (int kk = 0; kk < 4; kk++) {
            const int k  = 4 * ko + kk;
            const int bi = k & 1;
            float ea = __expf(ev[kk].x);
            float eb = __expf(ev[kk].y);
            int   mk = mv[kk];
            float2 ev_n = *(const float2*)(ep0 + (long)(k + 4) * rstride);
            int    mv_n = mrow[srow0 + (k + 4) * sstep];

            // value to publish: fwd = u, bwd = e_s ∘ v
            float pa  = isBwd ? (ua * ea) : ua;
            float pbv = isBwd ? (ub * eb) : ub;

            // publish-time exact power-of-two normalization (band ~2^-4)
            float p0 = __shfl_sync(0xffffffffu, pa, 0);
            int   e0 = ((__float_as_int(p0) >> 23) & 0xff) - 127 + 4;
            float sc = __int_as_float((127 - e0) << 23);   // 2^-e0, exact

            // natural-pair publish: one cvt + one STS.32
            __half2 h2 = __floats2half2_rn(pa * sc, pbv * sc);
            unsigned int* pb = bi ? myb1 : myb0;
            pb[t] = *(unsigned int*)&h2;
            __syncwarp(0xffffffffu);

            float2 o = dot_fp16(pb, EA, EB);

            // output: fwd folds emission of step s; bwd does not
            float na = isBwd ? o.x : (o.x * ea);
            float nb = isBwd ? o.y : (o.y * eb);
            const bool keep = (mk != 0);
            ua = keep ? na : ua;
            ub = keep ? nb : ub;
            eoff += e0 & (-mk);
            ev[kk] = ev_n; mv[kk] = mv_n;
        }
    }

    // midpoint vectors (fp32 state)
    fv[bs][dir][j0] = ua;
    fv[bs][dir][j1] = ub;

    // ---- numerator partial over this warp's half of S + mask count ----
    float npart = 0.0f; int mcount = 0;
    const size_t tbase = (size_t)b * NS;
    const int sBeg = dir ? (NS / 2) : 0;
    const int sEnd = sBeg + NS / 2;
    for (int s = sBeg + t; s < sEnd; s += 32) {
        size_t idx = tbase + s;
        int tg = is64 ? tags32[2 * idx] : tags32[idx];
        float emv = emb[s * NT + tg];
        if (s == 0) {
            npart += startT[tg] + emv;
        } else if (mrow[s]) {
            size_t idp = tbase + s - 1;
            int tp = is64 ? tags32[2 * idp] : tags32[idp];
            npart += trans[tp * NT + tg] + emv;
        }
        mcount += (mrow[s] != 0);
    }
    npart  = warp_sum_f(npart);
    mcount = warp_sum_i(mcount);
    if (t == 0) { nsh[w] = npart; msh[w] = mcount; eosh[w] = eoff; }
    __syncthreads();

    // ---- combine: dir==0 warp of each batch slot ----
    if (dir == 0) {
        float z = fv[bs][0][j0] * fv[bs][1][j0]
                + fv[bs][0][j1] * fv[bs][1][j1];
        z = warp_sum_f(z);
        if (t == 0) {
            int   etot = eosh[2 * bs] + eosh[2 * bs + 1];
            int   mc   = msh[2 * bs] + msh[2 * bs + 1];
            float ns   = nsh[2 * bs] + nsh[2 * bs + 1];
            size_t lidx = tbase + (mc - 1);
            int last = is64 ? tags32[2 * lidx] : tags32[lidx];
            ns += endT[last];
            double denom = (double)etot * 0.6931471805599453 + (double)logf(z);
            g_llh[b] = (float)(denom - (double)ns);

            __threadfence();
            int ticket = atomicAdd(&g_cnt, 1);
            if (ticket == NB - 1) {
                float acc = 0.0f;
#pragma unroll 8
                for (int i = 0; i < NB; i++) acc += __ldcg(&g_llh[i]);
                *out = acc / (float)NB;
                g_cnt = 0;                    // self-reset for graph replay
            }
        }
    }
}

extern "C" void kernel_launch(void* const* d_in, const int* in_sizes, int n_in,
                              void* d_out, int out_size)
{
    const float* em   = (const float*)d_in[0];
    const int*   tags = (const int*)d_in[1];
    const int*   mask = (const int*)d_in[2];
    const float* st   = (const float*)d_in[3];
    const float* en   = (const float*)d_in[4];
    const float* tr   = (const float*)d_in[5];

    crf_forward_kernel<<<NB / 4, 256>>>(em, tags, mask, st, en, tr, (float*)d_out);
}

// round 16
// speedup vs baseline: 2.2123x; 2.2123x over previous
#include <cuda_runtime.h>
#include <cuda_fp16.h>

// CRF NLL mean — B=256, S=512, T=64.
// Bidirectional split (fwd: transitions 1..255, bwd: 511..256) combined at the
// midpoint. One self-contained warp per chain. R16: R15's lean fp16 step
// (natural-pair STS.32 publish, 8 LDS.128 + 64 HFMA2) at R13's topology:
// block = 4 warps = 2 batches x {fwd,bwd}, grid = 128 -> 1 block/SM,
// exactly ONE chain per SMSP (R15 proved SMSPs saturate at one chain).

constexpr int NT  = 64;
constexpr int NB  = 256;
constexpr int NS  = 512;

__device__ float g_llh[NB];
__device__ int   g_cnt = 0;

__device__ __forceinline__ float warp_sum_f(float v) {
#pragma unroll
    for (int o = 16; o > 0; o >>= 1) v += __shfl_down_sync(0xffffffffu, v, o);
    return v;
}
__device__ __forceinline__ int warp_sum_i(int v) {
#pragma unroll
    for (int o = 16; o > 0; o >>= 1) v += __shfl_down_sync(0xffffffffu, v, o);
    return v;
}

// Parity-split 64-contraction in fp16. pb: 32 half2 words, word k = (u_2k,u_2k+1).
// EA[k] = (E_{2k}->j0, E_{2k+1}->j0), EB likewise for j1. Outputs = lo+hi.
__device__ __forceinline__ float2 dot_fp16(
    const unsigned int* __restrict__ pb,
    const __half2* __restrict__ EA, const __half2* __restrict__ EB)
{
    __half2 z = __float2half2_rn(0.0f);
    __half2 a0=z,a1=z,a2=z,a3=z,b0=z,b1=z,b2=z,b3=z;
    const uint4* p4 = (const uint4*)pb;   // 8 x 16B broadcast reads
#pragma unroll
    for (int g = 0; g < 8; g += 2) {
        uint4 q0 = p4[g];
        uint4 q1 = p4[g + 1];
        a0 = __hfma2(*(const __half2*)&q0.x, EA[4*g + 0], a0);
        b0 = __hfma2(*(const __half2*)&q0.x, EB[4*g + 0], b0);
        a1 = __hfma2(*(const __half2*)&q0.y, EA[4*g + 1], a1);
        b1 = __hfma2(*(const __half2*)&q0.y, EB[4*g + 1], b1);
        a2 = __hfma2(*(const __half2*)&q0.z, EA[4*g + 2], a2);
        b2 = __hfma2(*(const __half2*)&q0.z, EB[4*g + 2], b2);
        a3 = __hfma2(*(const __half2*)&q0.w, EA[4*g + 3], a3);
        b3 = __hfma2(*(const __half2*)&q0.w, EB[4*g + 3], b3);
        a0 = __hfma2(*(const __half2*)&q1.x, EA[4*g + 4], a0);
        b0 = __hfma2(*(const __half2*)&q1.x, EB[4*g + 4], b0);
        a1 = __hfma2(*(const __half2*)&q1.y, EA[4*g + 5], a1);
        b1 = __hfma2(*(const __half2*)&q1.y, EB[4*g + 5], b1);
        a2 = __hfma2(*(const __half2*)&q1.z, EA[4*g + 6], a2);
        b2 = __hfma2(*(const __half2*)&q1.z, EB[4*g + 6], b2);
        a3 = __hfma2(*(const __half2*)&q1.w, EA[4*g + 7], a3);
        b3 = __hfma2(*(const __half2*)&q1.w, EB[4*g + 7], b3);
    }
    a0 = __hadd2(a0, a1); a2 = __hadd2(a2, a3); a0 = __hadd2(a0, a2);
    b0 = __hadd2(b0, b1); b2 = __hadd2(b2, b3); b0 = __hadd2(b0, b2);
    float2 fa = __half22float2(a0);
    float2 fb = __half22float2(b0);
    return make_float2(fa.x + fa.y, fb.x + fb.y);
}

__global__ __launch_bounds__(128, 1) void crf_forward_kernel(
    const float* __restrict__ em,        // (B,S,T)
    const int*   __restrict__ tags32,    // (B,S) int32 (or int64 viewed as pairs)
    const int*   __restrict__ mask,      // (B,S)
    const float* __restrict__ startT,
    const float* __restrict__ endT,
    const float* __restrict__ trans,
    float*       __restrict__ out)
{
    const int tid = threadIdx.x;
    const int w   = tid >> 5;            // warp 0..3 -> SMSP 0..3
    const int t   = tid & 31;            // lane; owns outputs j0=2t, j1=2t+1
    const int bs  = w >> 1;              // batch slot 0..1
    const int dir = w & 1;               // 0 = forward, 1 = backward
    const int b   = blockIdx.x * 2 + bs;

    // per-warp double-buffered published vector: 32 half2 words = 128B
    __shared__ __align__(16) unsigned int ubuf[4][2][32];
    __shared__ float fv[2][2][NT];
    __shared__ float nsh[4];
    __shared__ int   msh[4], eosh[4];

    bool is64 = true;
#pragma unroll
    for (int k = 0; k < 16; k++) is64 &= (tags32[2 * k + 1] == 0);

    const int j0 = 2 * t, j1 = 2 * t + 1;

    // E in fp16, parity-packed over contraction dim (64 half2 = 64 regs)
    __half2 EA[32], EB[32];
    if (dir == 0) {
        // fwd: contraction over rows i; outputs = columns j0/j1
#pragma unroll
        for (int k = 0; k < 32; k++) {
            float a0 = __expf(trans[(2 * k)     * NT + j0]);
            float a1 = __expf(trans[(2 * k + 1) * NT + j0]);
            float b0 = __expf(trans[(2 * k)     * NT + j1]);
            float b1 = __expf(trans[(2 * k + 1) * NT + j1]);
            EA[k] = __floats2half2_rn(a0, a1);
            EB[k] = __floats2half2_rn(b0, b1);
        }
    } else {
        // bwd: contraction over columns; outputs = rows j0/j1
#pragma unroll
        for (int k = 0; k < 32; k++) {
            float2 rA = *(const float2*)(trans + j0 * NT + 2 * k);
            float2 rB = *(const float2*)(trans + j1 * NT + 2 * k);
            EA[k] = __floats2half2_rn(__expf(rA.x), __expf(rA.y));
            EB[k] = __floats2half2_rn(__expf(rB.x), __expf(rB.y));
        }
    }

    const float* emb  = em + (size_t)b * NS * NT;
    const int*   mrow = mask + b * NS;
    unsigned int* myb0 = ubuf[w][0];
    unsigned int* myb1 = ubuf[w][1];

    const int  srow0 = dir ? (NS - 1) : 0;
    const int  sstep = dir ? -1 : 1;
    const float* ep0 = emb + srow0 * NT + j0;
    const long rstride = (long)sstep * NT;

    float ua, ub;                         // fp32 chain state
    int eoff = 0;
    if (dir == 0) {
        float2 st2 = *(const float2*)(startT + j0);
        float2 e0v = *(const float2*)(emb + j0);
        ua = __expf(st2.x + e0v.x);
        ub = __expf(st2.y + e0v.y);
    } else {
        float2 en2 = *(const float2*)(endT + j0);
        ua = __expf(en2.x);
        ub = __expf(en2.y);
    }
    const int isBwd = dir;

    // depth-4 rotating prefetch (always in-bounds)
    float2 ev[4]; int mv[4];
#pragma unroll
    for (int k = 0; k < 4; k++) {
        ev[k] = *(const float2*)(ep0 + (long)k * rstride);
        mv[k] = mrow[srow0 + k * sstep];
    }
    if (dir == 0) mv[0] = 0;              // fwd dummy step

    for (int ko = 0; ko < 64; ko++) {
#pragma unroll
        for (int kk = 0; kk < 4; kk++) {
            const int k  = 4 * ko + kk;
            const int bi = k & 1;
            float ea = __expf(ev[kk].x);
            float eb = __expf(ev[kk].y);
            int   mk = mv[kk];
            float2 ev_n = *(const float2*)(ep0 + (long)(k + 4) * rstride);
            int    mv_n = mrow[srow0 + (k + 4) * sstep];

            // value to publish: fwd = u, bwd = e_s ∘ v
            float pa  = isBwd ? (ua * ea) : ua;
            float pbv = isBwd ? (ub * eb) : ub;

            // publish-time exact power-of-two normalization (band ~2^-4)
            float p0 = __shfl_sync(0xffffffffu, pa, 0);
            int   e0 = ((__float_as_int(p0) >> 23) & 0xff) - 127 + 4;
            float sc = __int_as_float((127 - e0) << 23);   // 2^-e0, exact

            // natural-pair publish: one cvt + one STS.32
            __half2 h2 = __floats2half2_rn(pa * sc, pbv * sc);
            unsigned int* pb = bi ? myb1 : myb0;
            pb[t] = *(unsigned int*)&h2;
            __syncwarp(0xffffffffu);

            float2 o = dot_fp16(pb, EA, EB);

            // output: fwd folds emission of step s; bwd does not
            float na = isBwd ? o.x : (o.x * ea);
            float nb = isBwd ? o.y : (o.y * eb);
            const bool keep = (mk != 0);
            ua = keep ? na : ua;
            ub = keep ? nb : ub;
            eoff += e0 & (-mk);
            ev[kk] = ev_n; mv[kk] = mv_n;
        }
    }

    // midpoint vectors (fp32 state)
    fv[bs][dir][j0] = ua;
    fv[bs][dir][j1] = ub;

    // ---- numerator partial over this warp's half of S + mask count ----
    float npart = 0.0f; int mcount = 0;
    const size_t tbase = (size_t)b * NS;
    const int sBeg = dir ? (NS / 2) : 0;
    const int sEnd = sBeg + NS / 2;
    for (int s = sBeg + t; s < sEnd; s += 32) {
        size_t idx = tbase + s;
        int tg = is64 ? tags32[2 * idx] : tags32[idx];
        float emv = emb[s * NT + tg];
        if (s == 0) {
            npart += startT[tg] + emv;
        } else if (mrow[s]) {
            size_t idp = tbase + s - 1;
            int tp = is64 ? tags32[2 * idp] : tags32[idp];
            npart += trans[tp * NT + tg] + emv;
        }
        mcount += (mrow[s] != 0);
    }
    npart  = warp_sum_f(npart);
    mcount = warp_sum_i(mcount);
    if (t == 0) { nsh[w] = npart; msh[w] = mcount; eosh[w] = eoff; }
    __syncthreads();

    // ---- combine: dir==0 warp of each batch slot ----
    if (dir == 0) {
        float z = fv[bs][0][j0] * fv[bs][1][j0]
                + fv[bs][0][j1] * fv[bs][1][j1];
        z = warp_sum_f(z);
        if (t == 0) {
            int   etot = eosh[2 * bs] + eosh[2 * bs + 1];
            int   mc   = msh[2 * bs] + msh[2 * bs + 1];
            float ns   = nsh[2 * bs] + nsh[2 * bs + 1];
            size_t lidx = tbase + (mc - 1);
            int last = is64 ? tags32[2 * lidx] : tags32[lidx];
            ns += endT[last];
            double denom = (double)etot * 0.6931471805599453 + (double)logf(z);
            g_llh[b] = (float)(denom - (double)ns);

            __threadfence();
            int ticket = atomicAdd(&g_cnt, 1);
            if (ticket == NB - 1) {
                float acc = 0.0f;
#pragma unroll 8
                for (int i = 0; i < NB; i++) acc += __ldcg(&g_llh[i]);
                *out = acc / (float)NB;
                g_cnt = 0;                    // self-reset for graph replay
            }
        }
    }
}

extern "C" void kernel_launch(void* const* d_in, const int* in_sizes, int n_in,
                              void* d_out, int out_size)
{
    const float* em   = (const float*)d_in[0];
    const int*   tags = (const int*)d_in[1];
    const int*   mask = (const int*)d_in[2];
    const float* st   = (const float*)d_in[3];
    const float* en   = (const float*)d_in[4];
    const float* tr   = (const float*)d_in[5];

    crf_forward_kernel<<<NB / 2, 128>>>(em, tags, mask, st, en, tr, (float*)d_out);
}

// round 17
// speedup vs baseline: 2.2302x; 1.0081x over previous
#include <cuda_runtime.h>
#include <cuda_fp16.h>

// CRF NLL mean — B=256, S=512, T=64.
// Bidirectional split (fwd: transitions 1..255, bwd: 511..256) combined at the
// midpoint. One self-contained warp per chain; block = 4 warps = 2 batches x
// {fwd,bwd}; grid = 128 -> 1 block/SM, one chain per SMSP.
// R17 = R16 with the renormalizer (shfl + exponent + scale pack) hoisted off
// the per-step critical path: computed from the updated state at the END of
// the previous step, overlapping its latency with prefetch/expf.

constexpr int NT  = 64;
constexpr int NB  = 256;
constexpr int NS  = 512;

__device__ float g_llh[NB];
__device__ int   g_cnt = 0;

__device__ __forceinline__ float warp_sum_f(float v) {
#pragma unroll
    for (int o = 16; o > 0; o >>= 1) v += __shfl_down_sync(0xffffffffu, v, o);
    return v;
}
__device__ __forceinline__ int warp_sum_i(int v) {
#pragma unroll
    for (int o = 16; o > 0; o >>= 1) v += __shfl_down_sync(0xffffffffu, v, o);
    return v;
}

// Parity-split 64-contraction in fp16. pb: 32 half2 words, word k = (u_2k,u_2k+1).
// EA[k] = (E_{2k}->j0, E_{2k+1}->j0), EB likewise for j1. Outputs = lo+hi.
__device__ __forceinline__ float2 dot_fp16(
    const unsigned int* __restrict__ pb,
    const __half2* __restrict__ EA, const __half2* __restrict__ EB)
{
    __half2 z = __float2half2_rn(0.0f);
    __half2 a0=z,a1=z,a2=z,a3=z,b0=z,b1=z,b2=z,b3=z;
    const uint4* p4 = (const uint4*)pb;   // 8 x 16B broadcast reads
#pragma unroll
    for (int g = 0; g < 8; g += 2) {
        uint4 q0 = p4[g];
        uint4 q1 = p4[g + 1];
        a0 = __hfma2(*(const __half2*)&q0.x, EA[4*g + 0], a0);
        b0 = __hfma2(*(const __half2*)&q0.x, EB[4*g + 0], b0);
        a1 = __hfma2(*(const __half2*)&q0.y, EA[4*g + 1], a1);
        b1 = __hfma2(*(const __half2*)&q0.y, EB[4*g + 1], b1);
        a2 = __hfma2(*(const __half2*)&q0.z, EA[4*g + 2], a2);
        b2 = __hfma2(*(const __half2*)&q0.z, EB[4*g + 2], b2);
        a3 = __hfma2(*(const __half2*)&q0.w, EA[4*g + 3], a3);
        b3 = __hfma2(*(const __half2*)&q0.w, EB[4*g + 3], b3);
        a0 = __hfma2(*(const __half2*)&q1.x, EA[4*g + 4], a0);
        b0 = __hfma2(*(const __half2*)&q1.x, EB[4*g + 4], b0);
        a1 = __hfma2(*(const __half2*)&q1.y, EA[4*g + 5], a1);
        b1 = __hfma2(*(const __half2*)&q1.y, EB[4*g + 5], b1);
        a2 = __hfma2(*(const __half2*)&q1.z, EA[4*g + 6], a2);
        b2 = __hfma2(*(const __half2*)&q1.z, EB[4*g + 6], b2);
        a3 = __hfma2(*(const __half2*)&q1.w, EA[4*g + 7], a3);
        b3 = __hfma2(*(const __half2*)&q1.w, EB[4*g + 7], b3);
    }
    a0 = __hadd2(a0, a1); a2 = __hadd2(a2, a3); a0 = __hadd2(a0, a2);
    b0 = __hadd2(b0, b1); b2 = __hadd2(b2, b3); b0 = __hadd2(b0, b2);
    float2 fa = __half22float2(a0);
    float2 fb = __half22float2(b0);
    return make_float2(fa.x + fa.y, fb.x + fb.y);
}

__global__ __launch_bounds__(128, 1) void crf_forward_kernel(
    const float* __restrict__ em,        // (B,S,T)
    const int*   __restrict__ tags32,    // (B,S) int32 (or int64 viewed as pairs)
    const int*   __restrict__ mask,      // (B,S)
    const float* __restrict__ startT,
    const float* __restrict__ endT,
    const float* __restrict__ trans,
    float*       __restrict__ out)
{
    const int tid = threadIdx.x;
    const int w   = tid >> 5;            // warp 0..3 -> SMSP 0..3
    const int t   = tid & 31;            // lane; owns outputs j0=2t, j1=2t+1
    const int bs  = w >> 1;              // batch slot 0..1
    const int dir = w & 1;               // 0 = forward, 1 = backward
    const int b   = blockIdx.x * 2 + bs;

    // per-warp double-buffered published vector: 32 half2 words = 128B
    __shared__ __align__(16) unsigned int ubuf[4][2][32];
    __shared__ float fv[2][2][NT];
    __shared__ float nsh[4];
    __shared__ int   msh[4], eosh[4];

    bool is64 = true;
#pragma unroll
    for (int k = 0; k < 16; k++) is64 &= (tags32[2 * k + 1] == 0);

    const int j0 = 2 * t, j1 = 2 * t + 1;

    // E in fp16, parity-packed over contraction dim (64 half2 = 64 regs)
    __half2 EA[32], EB[32];
    if (dir == 0) {
#pragma unroll
        for (int k = 0; k < 32; k++) {
            float a0 = __expf(trans[(2 * k)     * NT + j0]);
            float a1 = __expf(trans[(2 * k + 1) * NT + j0]);
            float b0 = __expf(trans[(2 * k)     * NT + j1]);
            float b1 = __expf(trans[(2 * k + 1) * NT + j1]);
            EA[k] = __floats2half2_rn(a0, a1);
            EB[k] = __floats2half2_rn(b0, b1);
        }
    } else {
#pragma unroll
        for (int k = 0; k < 32; k++) {
            float2 rA = *(const float2*)(trans + j0 * NT + 2 * k);
            float2 rB = *(const float2*)(trans + j1 * NT + 2 * k);
            EA[k] = __floats2half2_rn(__expf(rA.x), __expf(rA.y));
            EB[k] = __floats2half2_rn(__expf(rB.x), __expf(rB.y));
        }
    }

    const float* emb  = em + (size_t)b * NS * NT;
    const int*   mrow = mask + b * NS;
    unsigned int* myb0 = ubuf[w][0];
    unsigned int* myb1 = ubuf[w][1];

    const int  srow0 = dir ? (NS - 1) : 0;
    const int  sstep = dir ? -1 : 1;
    const float* ep0 = emb + srow0 * NT + j0;
    const long rstride = (long)sstep * NT;

    float ua, ub;                         // fp32 chain state
    int eoff = 0;
    if (dir == 0) {
        float2 st2 = *(const float2*)(startT + j0);
        float2 e0v = *(const float2*)(emb + j0);
        ua = __expf(st2.x + e0v.x);
        ub = __expf(st2.y + e0v.y);
    } else {
        float2 en2 = *(const float2*)(endT + j0);
        ua = __expf(en2.x);
        ub = __expf(en2.y);
    }
    const int isBwd = dir;

    // depth-4 rotating prefetch (always in-bounds)
    float2 ev[4]; int mv[4];
#pragma unroll
    for (int k = 0; k < 4; k++) {
        ev[k] = *(const float2*)(ep0 + (long)k * rstride);
        mv[k] = mrow[srow0 + k * sstep];
    }
    if (dir == 0) mv[0] = 0;              // fwd dummy step

    // Hoisted renormalizer: scale for the NEXT publish, derived from current
    // state's lane-0 value (exact power of two; latency overlaps loop tail).
    float p0h = __shfl_sync(0xffffffffu, ua, 0);
    int   e0c = ((__float_as_int(p0h) >> 23) & 0xff) - 123;   // expo + 4
    float scc = __int_as_float((127 - e0c) << 23);            // 2^-e0c, exact

    for (int ko = 0; ko < 64; ko++) {
#pragma unroll
        for (int kk = 0; kk < 4; kk++) {
            const int k  = 4 * ko + kk;
            const int bi = k & 1;
            float ea = __expf(ev[kk].x);
            float eb = __expf(ev[kk].y);
            int   mk = mv[kk];
            float2 ev_n = *(const float2*)(ep0 + (long)(k + 4) * rstride);
            int    mv_n = mrow[srow0 + (k + 4) * sstep];

            // value to publish: fwd = u, bwd = e_s ∘ v  (scale already ready)
            float pa  = isBwd ? (ua * ea) : ua;
            float pbv = isBwd ? (ub * eb) : ub;

            __half2 h2 = __floats2half2_rn(pa * scc, pbv * scc);
            unsigned int* pb = bi ? myb1 : myb0;
            pb[t] = *(unsigned int*)&h2;
            __syncwarp(0xffffffffu);

            float2 o = dot_fp16(pb, EA, EB);

            // output: fwd folds emission of step s; bwd does not
            float na = isBwd ? o.x : (o.x * ea);
            float nb = isBwd ? o.y : (o.y * eb);
            const bool keep = (mk != 0);
            ua = keep ? na : ua;
            ub = keep ? nb : ub;
            eoff += e0c & (-mk);

            // hoist next-step renormalizer off the critical path
            float p0n = __shfl_sync(0xffffffffu, ua, 0);
            e0c = ((__float_as_int(p0n) >> 23) & 0xff) - 123;
            scc = __int_as_float((127 - e0c) << 23);

            ev[kk] = ev_n; mv[kk] = mv_n;
        }
    }

    // midpoint vectors (fp32 state)
    fv[bs][dir][j0] = ua;
    fv[bs][dir][j1] = ub;

    // ---- numerator partial over this warp's half of S + mask count ----
    float npart = 0.0f; int mcount = 0;
    const size_t tbase = (size_t)b * NS;
    const int sBeg = dir ? (NS / 2) : 0;
    const int sEnd = sBeg + NS / 2;
    for (int s = sBeg + t; s < sEnd; s += 32) {
        size_t idx = tbase + s;
        int tg = is64 ? tags32[2 * idx] : tags32[idx];
        float emv = emb[s * NT + tg];
        if (s == 0) {
            npart += startT[tg] + emv;
        } else if (mrow[s]) {
            size_t idp = tbase + s - 1;
            int tp = is64 ? tags32[2 * idp] : tags32[idp];
            npart += trans[tp * NT + tg] + emv;
        }
        mcount += (mrow[s] != 0);
    }
    npart  = warp_sum_f(npart);
    mcount = warp_sum_i(mcount);
    if (t == 0) { nsh[w] = npart; msh[w] = mcount; eosh[w] = eoff; }
    __syncthreads();

    // ---- combine: dir==0 warp of each batch slot ----
    if (dir == 0) {
        float z = fv[bs][0][j0] * fv[bs][1][j0]
                + fv[bs][0][j1] * fv[bs][1][j1];
        z = warp_sum_f(z);
        if (t == 0) {
            int   etot = eosh[2 * bs] + eosh[2 * bs + 1];
            int   mc   = msh[2 * bs] + msh[2 * bs + 1];
            float ns   = nsh[2 * bs] + nsh[2 * bs + 1];
            size_t lidx = tbase + (mc - 1);
            int last = is64 ? tags32[2 * lidx] : tags32[lidx];
            ns += endT[last];
            double denom = (double)etot * 0.6931471805599453 + (double)logf(z);
            g_llh[b] = (float)(denom - (double)ns);

            __threadfence();
            int ticket = atomicAdd(&g_cnt, 1);
            if (ticket == NB - 1) {
                float acc = 0.0f;
#pragma unroll 8
                for (int i = 0; i < NB; i++) acc += __ldcg(&g_llh[i]);
                *out = acc / (float)NB;
                g_cnt = 0;                    // self-reset for graph replay
            }
        }
    }
}

extern "C" void kernel_launch(void* const* d_in, const int* in_sizes, int n_in,
                              void* d_out, int out_size)
{
    const float* em   = (const float*)d_in[0];
    const int*   tags = (const int*)d_in[1];
    const int*   mask = (const int*)d_in[2];
    const float* st   = (const float*)d_in[3];
    const float* en   = (const float*)d_in[4];
    const float* tr   = (const float*)d_in[5];

    crf_forward_kernel<<<NB / 2, 128>>>(em, tags, mask, st, en, tr, (float*)d_out);
}